// round 3
// baseline (speedup 1.0000x reference)
#include <cuda_runtime.h>
#include <cuda_bf16.h>
#include <cstdint>

#define BB 64
#define SS 2048
#define DD 1024
#define SPLITS 16
#define S_PER (SS / SPLITS)   // 128

// Scratch (allocation-free rule: __device__ global)
__device__ float g_partial[SPLITS * BB * DD];      // 4 MB

// ---------------------------------------------------------------------------
// Fused pool kernel: per-CTA mask count (L2-resident, 8KB/batch) + inline
// weight computation + deterministic ballot compaction + MLP=8 gather.
// grid = (SPLITS, BB), block = 256. Each thread owns one float4 of D.
// ---------------------------------------------------------------------------
__global__ void __launch_bounds__(256)
pool_kernel(const float* __restrict__ hidden, const int* __restrict__ mask) {
    const int b     = blockIdx.y;
    const int split = blockIdx.x;
    const int s0    = split * S_PER;
    const int tid   = threadIdx.x;

    __shared__ float s_w[S_PER];
    __shared__ short s_idx[S_PER];
    __shared__ int   s_warpcnt[4];
    __shared__ int   s_n;
    __shared__ int   s_cnt[8];

    // ---- Phase 1: count full-batch mask (2048 ints = 2 int4 per thread) ----
    const int4* m4 = (const int4*)(mask + b * SS);
    const int4  c0 = m4[tid];
    const int4  c1 = m4[tid + 256];
    int sum = c0.x + c0.y + c0.z + c0.w + c1.x + c1.y + c1.z + c1.w;
    #pragma unroll
    for (int o = 16; o > 0; o >>= 1)
        sum += __shfl_xor_sync(0xFFFFFFFFu, sum, o);
    if ((tid & 31) == 0) s_cnt[tid >> 5] = sum;
    __syncthreads();
    int cnt = 0;
    #pragma unroll
    for (int i = 0; i < 8; i++) cnt += s_cnt[i];

    const float inv = (cnt > 0) ? (1.0f / (float)cnt) : (1.0f / (float)SS);

    // ---- Phase 2: inline weights for this split + deterministic compaction ----
    float    myw  = 0.0f;
    unsigned ball = 0;
    if (tid < S_PER) {
        const int mv = mask[b * SS + s0 + tid];      // L2 hit
        myw  = (cnt > 0) ? (mv ? inv : 0.0f) : inv;
        ball = __ballot_sync(0xFFFFFFFFu, myw != 0.0f);
        if ((tid & 31) == 0) s_warpcnt[tid >> 5] = __popc(ball);
    }
    __syncthreads();

    if (tid < S_PER) {
        const int warp = tid >> 5, lane = tid & 31;
        if (myw != 0.0f) {
            int base = 0;
            #pragma unroll
            for (int i = 0; i < 4; i++) if (i < warp) base += s_warpcnt[i];
            const int pos = base + __popc(ball & ((1u << lane) - 1u));
            s_idx[pos] = (short)tid;
            s_w[pos]   = myw;
        }
        if (tid == 0)
            s_n = s_warpcnt[0] + s_warpcnt[1] + s_warpcnt[2] + s_warpcnt[3];
    }
    __syncthreads();

    const int n = s_n;
    const float* rowbase = hidden + (size_t)b * SS * DD + (size_t)s0 * DD + (size_t)tid * 4;

    float ax = 0.0f, ay = 0.0f, az = 0.0f, aw = 0.0f;

    // ---- Phase 3: gather-reduce, 8 independent 16B loads in flight ----
    int i = 0;
    for (; i + 8 <= n; i += 8) {
        int   r[8];
        float w[8];
        #pragma unroll
        for (int j = 0; j < 8; j++) { r[j] = s_idx[i + j]; w[j] = s_w[i + j]; }
        float4 v[8];
        #pragma unroll
        for (int j = 0; j < 8; j++)
            v[j] = *(const float4*)(rowbase + (size_t)r[j] * DD);
        #pragma unroll
        for (int j = 0; j < 8; j++) {
            ax = fmaf(w[j], v[j].x, ax); ay = fmaf(w[j], v[j].y, ay);
            az = fmaf(w[j], v[j].z, az); aw = fmaf(w[j], v[j].w, aw);
        }
    }
    for (; i < n; i++) {
        const int   r = s_idx[i];
        const float w = s_w[i];
        const float4 v = *(const float4*)(rowbase + (size_t)r * DD);
        ax = fmaf(w, v.x, ax); ay = fmaf(w, v.y, ay);
        az = fmaf(w, v.z, az); aw = fmaf(w, v.w, aw);
    }

    float4 out;
    out.x = ax; out.y = ay; out.z = az; out.w = aw;
    ((float4*)g_partial)[(size_t)(split * BB + b) * (DD / 4) + tid] = out;
}

// ---------------------------------------------------------------------------
// Combine SPLITS partials -> d_out. grid = 64, block = 256.
// ---------------------------------------------------------------------------
__global__ void combine_kernel(float* __restrict__ out) {
    const int idx = blockIdx.x * 256 + threadIdx.x;   // over B*D/4 = 16384
    const int b = idx / (DD / 4);
    const int c = idx % (DD / 4);

    float ax = 0.0f, ay = 0.0f, az = 0.0f, aw = 0.0f;
    #pragma unroll
    for (int sp = 0; sp < SPLITS; sp++) {
        const float4 v = ((const float4*)g_partial)[(size_t)(sp * BB + b) * (DD / 4) + c];
        ax += v.x; ay += v.y; az += v.z; aw += v.w;
    }
    float4 o;
    o.x = ax; o.y = ay; o.z = az; o.w = aw;
    ((float4*)out)[idx] = o;
}

// ---------------------------------------------------------------------------
extern "C" void kernel_launch(void* const* d_in, const int* in_sizes, int n_in,
                              void* d_out, int out_size) {
    const float* hidden = (const float*)d_in[0];
    const int*   mask   = (const int*)d_in[1];
    float*       out    = (float*)d_out;

    dim3 grid(SPLITS, BB);
    pool_kernel<<<grid, 256>>>(hidden, mask);
    combine_kernel<<<(BB * DD / 4) / 256, 256>>>(out);
}

// round 5
// speedup vs baseline: 1.1188x; 1.1188x over previous
#include <cuda_runtime.h>
#include <cuda_bf16.h>
#include <cstdint>

#define BB 64
#define SS 2048
#define DD 1024
#define SPLITS 8
#define S_PER (SS / SPLITS)   // 256 == blockDim

// Scratch (allocation-free rule: __device__ globals)
__device__ int   g_cnt[BB];                        // 256 B
__device__ float g_partial[SPLITS * BB * DD];      // 2 MB

// ---------------------------------------------------------------------------
// Kernel 1: per-batch mask count. grid=64, block=1024 -> each thread loads
// one int2 (single DRAM round trip of latency), tree-reduce, write 1 int.
// ---------------------------------------------------------------------------
__global__ void __launch_bounds__(1024)
count_kernel(const int* __restrict__ mask) {
    const int b   = blockIdx.x;
    const int tid = threadIdx.x;

    const int2 v = ((const int2*)(mask + b * SS))[tid];   // 1024*2 = 2048
    int sum = v.x + v.y;
    #pragma unroll
    for (int o = 16; o > 0; o >>= 1)
        sum += __shfl_xor_sync(0xFFFFFFFFu, sum, o);

    __shared__ int ws[32];
    if ((tid & 31) == 0) ws[tid >> 5] = sum;
    __syncthreads();
    if (tid < 32) {
        int s = ws[tid];
        #pragma unroll
        for (int o = 16; o > 0; o >>= 1)
            s += __shfl_xor_sync(0xFFFFFFFFu, s, o);
        if (tid == 0) g_cnt[b] = s;
    }
}

// ---------------------------------------------------------------------------
// Kernel 2: weighted reduction over an S-split of 256 rows. Inline weights
// from g_cnt + L2-hot mask read; deterministic ballot compaction skips
// zero-weight rows (~50% HBM traffic saved); MLP=4 gather.
// grid = (SPLITS, BB), block = 256. Each thread owns one float4 of D.
// ---------------------------------------------------------------------------
__global__ void __launch_bounds__(256)
pool_kernel(const float* __restrict__ hidden, const int* __restrict__ mask) {
    const int b     = blockIdx.y;
    const int split = blockIdx.x;
    const int s0    = split * S_PER;
    const int tid   = threadIdx.x;

    __shared__ float s_w[S_PER];
    __shared__ short s_idx[S_PER];
    __shared__ int   s_warpcnt[8];

    const int   cnt = g_cnt[b];
    const float inv = (cnt > 0) ? (1.0f / (float)cnt) : (1.0f / (float)SS);

    // ---- weights for this split + deterministic compaction (256 == blockDim)
    const int mv = mask[b * SS + s0 + tid];               // L2 hit after count
    const float myw = (cnt > 0) ? (mv ? inv : 0.0f) : inv;
    const unsigned ball = __ballot_sync(0xFFFFFFFFu, myw != 0.0f);
    const int warp = tid >> 5, lane = tid & 31;
    if (lane == 0) s_warpcnt[warp] = __popc(ball);
    __syncthreads();

    int base = 0, n = 0;
    #pragma unroll
    for (int i = 0; i < 8; i++) {
        if (i < warp) base += s_warpcnt[i];
        n += s_warpcnt[i];
    }
    if (myw != 0.0f) {
        const int pos = base + __popc(ball & ((1u << lane) - 1u));
        s_idx[pos] = (short)tid;
        s_w[pos]   = myw;
    }
    __syncthreads();

    const float* rowbase = hidden + (size_t)b * SS * DD + (size_t)s0 * DD + (size_t)tid * 4;

    float ax = 0.0f, ay = 0.0f, az = 0.0f, aw = 0.0f;

    // ---- gather-reduce, 4 independent 16B loads in flight (R1-proven config)
    int i = 0;
    for (; i + 4 <= n; i += 4) {
        const int   r0 = s_idx[i + 0], r1 = s_idx[i + 1];
        const int   r2 = s_idx[i + 2], r3 = s_idx[i + 3];
        const float w0 = s_w[i + 0],   w1 = s_w[i + 1];
        const float w2 = s_w[i + 2],   w3 = s_w[i + 3];
        const float4 v0 = *(const float4*)(rowbase + (size_t)r0 * DD);
        const float4 v1 = *(const float4*)(rowbase + (size_t)r1 * DD);
        const float4 v2 = *(const float4*)(rowbase + (size_t)r2 * DD);
        const float4 v3 = *(const float4*)(rowbase + (size_t)r3 * DD);
        ax = fmaf(w0, v0.x, ax); ay = fmaf(w0, v0.y, ay);
        az = fmaf(w0, v0.z, az); aw = fmaf(w0, v0.w, aw);
        ax = fmaf(w1, v1.x, ax); ay = fmaf(w1, v1.y, ay);
        az = fmaf(w1, v1.z, az); aw = fmaf(w1, v1.w, aw);
        ax = fmaf(w2, v2.x, ax); ay = fmaf(w2, v2.y, ay);
        az = fmaf(w2, v2.z, az); aw = fmaf(w2, v2.w, aw);
        ax = fmaf(w3, v3.x, ax); ay = fmaf(w3, v3.y, ay);
        az = fmaf(w3, v3.z, az); aw = fmaf(w3, v3.w, aw);
    }
    for (; i < n; i++) {
        const int   r = s_idx[i];
        const float w = s_w[i];
        const float4 v = *(const float4*)(rowbase + (size_t)r * DD);
        ax = fmaf(w, v.x, ax); ay = fmaf(w, v.y, ay);
        az = fmaf(w, v.z, az); aw = fmaf(w, v.w, aw);
    }

    float4 out;
    out.x = ax; out.y = ay; out.z = az; out.w = aw;
    ((float4*)g_partial)[(size_t)(split * BB + b) * (DD / 4) + tid] = out;
}

// ---------------------------------------------------------------------------
// Kernel 3: combine 8 partials -> d_out. One scalar per thread for maximum
// latency-hiding parallelism: 65536 threads, coalesced.
// ---------------------------------------------------------------------------
__global__ void __launch_bounds__(256)
combine_kernel(float* __restrict__ out) {
    const int idx = blockIdx.x * 256 + threadIdx.x;   // over B*D = 65536
    const int b = idx >> 10;            // / DD
    const int d = idx & (DD - 1);

    float acc = 0.0f;
    #pragma unroll
    for (int sp = 0; sp < SPLITS; sp++)
        acc += g_partial[(size_t)(sp * BB + b) * DD + d];
    out[idx] = acc;
}

// ---------------------------------------------------------------------------
extern "C" void kernel_launch(void* const* d_in, const int* in_sizes, int n_in,
                              void* d_out, int out_size) {
    const float* hidden = (const float*)d_in[0];
    const int*   mask   = (const int*)d_in[1];
    float*       out    = (float*)d_out;

    count_kernel<<<BB, 1024>>>(mask);
    dim3 grid(SPLITS, BB);
    pool_kernel<<<grid, 256>>>(hidden, mask);
    combine_kernel<<<(BB * DD) / 256, 256>>>(out);
}

// round 6
// speedup vs baseline: 1.1195x; 1.0006x over previous
#include <cuda_runtime.h>
#include <cuda_bf16.h>
#include <cstdint>

#define BB 64
#define SS 2048
#define DD 1024
#define SPLITS 8
#define S_PER (SS / SPLITS)   // 256 == blockDim

// Scratch (allocation-free rule: __device__ globals)
__device__ int   g_scnt[SPLITS * BB];              // per-slice nonzero counts
__device__ float g_partial[SPLITS * BB * DD];      // 2 MB unweighted partial sums

// ---------------------------------------------------------------------------
// Pool kernel: per-slice UNWEIGHTED masked sum + slice count. No dependency
// on any precomputed global count — scaling happens in combine.
// grid = (SPLITS, BB), block = 256. Each thread owns one float4 of D.
// ---------------------------------------------------------------------------
__global__ void __launch_bounds__(256)
pool_kernel(const float* __restrict__ hidden, const int* __restrict__ mask) {
    const int b     = blockIdx.y;
    const int split = blockIdx.x;
    const int s0    = split * S_PER;
    const int tid   = threadIdx.x;

    __shared__ short s_idx[S_PER];
    __shared__ int   s_warpcnt[8];

    // ---- own-slice mask read (coalesced, 1KB) + deterministic compaction ----
    const int mv = mask[b * SS + s0 + tid];
    const unsigned ball = __ballot_sync(0xFFFFFFFFu, mv != 0);
    const int warp = tid >> 5, lane = tid & 31;
    if (lane == 0) s_warpcnt[warp] = __popc(ball);
    __syncthreads();

    int base = 0, n = 0;
    #pragma unroll
    for (int i = 0; i < 8; i++) {
        if (i < warp) base += s_warpcnt[i];
        n += s_warpcnt[i];
    }
    if (mv != 0) {
        const int pos = base + __popc(ball & ((1u << lane) - 1u));
        s_idx[pos] = (short)tid;
    }
    __syncthreads();

    // ---- rare corner: slice all-zero. Decide via full-batch mask scan. ----
    bool sum_all = false;
    if (n == 0) {
        int csum = 0;
        #pragma unroll
        for (int j = 0; j < SS / 256; j++)            // 8 strided ints/thread
            csum += mask[b * SS + j * 256 + tid];
        #pragma unroll
        for (int o = 16; o > 0; o >>= 1)
            csum += __shfl_xor_sync(0xFFFFFFFFu, csum, o);
        __shared__ int s_g[8];
        if (lane == 0) s_g[warp] = csum;
        __syncthreads();
        int cg = 0;
        #pragma unroll
        for (int i = 0; i < 8; i++) cg += s_g[i];
        sum_all = (cg == 0);                          // batch truly empty -> full mean
    }

    if (tid == 0) g_scnt[split * BB + b] = n;

    const float* rowbase = hidden + (size_t)b * SS * DD + (size_t)s0 * DD + (size_t)tid * 4;

    float ax = 0.0f, ay = 0.0f, az = 0.0f, aw = 0.0f;

    if (n > 0) {
        // ---- common path: gather-sum nonzero rows, MLP=4 ----
        int i = 0;
        for (; i + 4 <= n; i += 4) {
            const int r0 = s_idx[i + 0], r1 = s_idx[i + 1];
            const int r2 = s_idx[i + 2], r3 = s_idx[i + 3];
            const float4 v0 = *(const float4*)(rowbase + (size_t)r0 * DD);
            const float4 v1 = *(const float4*)(rowbase + (size_t)r1 * DD);
            const float4 v2 = *(const float4*)(rowbase + (size_t)r2 * DD);
            const float4 v3 = *(const float4*)(rowbase + (size_t)r3 * DD);
            ax += v0.x; ay += v0.y; az += v0.z; aw += v0.w;
            ax += v1.x; ay += v1.y; az += v1.z; aw += v1.w;
            ax += v2.x; ay += v2.y; az += v2.z; aw += v2.w;
            ax += v3.x; ay += v3.y; az += v3.z; aw += v3.w;
        }
        for (; i < n; i++) {
            const float4 v = *(const float4*)(rowbase + (size_t)s_idx[i] * DD);
            ax += v.x; ay += v.y; az += v.z; aw += v.w;
        }
    } else if (sum_all) {
        // ---- fallback: batch all-zero, sum ALL rows (full-mean numerator) ----
        for (int i = 0; i + 4 <= S_PER; i += 4) {
            const float4 v0 = *(const float4*)(rowbase + (size_t)(i + 0) * DD);
            const float4 v1 = *(const float4*)(rowbase + (size_t)(i + 1) * DD);
            const float4 v2 = *(const float4*)(rowbase + (size_t)(i + 2) * DD);
            const float4 v3 = *(const float4*)(rowbase + (size_t)(i + 3) * DD);
            ax += v0.x; ay += v0.y; az += v0.z; aw += v0.w;
            ax += v1.x; ay += v1.y; az += v1.z; aw += v1.w;
            ax += v2.x; ay += v2.y; az += v2.z; aw += v2.w;
            ax += v3.x; ay += v3.y; az += v3.z; aw += v3.w;
        }
    }
    // (n==0 && !sum_all): contribute zeros — partial MUST be written every
    // replay since g_partial persists across graph replays.

    float4 out;
    out.x = ax; out.y = ay; out.z = az; out.w = aw;
    ((float4*)g_partial)[(size_t)(split * BB + b) * (DD / 4) + tid] = out;
}

// ---------------------------------------------------------------------------
// Combine: cnt = sum of slice counts (L2-hot), inv = 1/max(cnt,?) per spec,
// out = inv * sum of partials. One scalar per thread, 65536 threads.
// ---------------------------------------------------------------------------
__global__ void __launch_bounds__(256)
combine_kernel(float* __restrict__ out) {
    const int idx = blockIdx.x * 256 + threadIdx.x;   // over B*D = 65536
    const int b = idx >> 10;            // / DD
    const int d = idx & (DD - 1);

    int cnt = 0;
    #pragma unroll
    for (int sp = 0; sp < SPLITS; sp++)
        cnt += g_scnt[sp * BB + b];                    // broadcast, L1/L2 hit
    const float inv = (cnt > 0) ? (1.0f / (float)cnt) : (1.0f / (float)SS);

    float acc = 0.0f;
    #pragma unroll
    for (int sp = 0; sp < SPLITS; sp++)
        acc += g_partial[(size_t)(sp * BB + b) * DD + d];
    out[idx] = acc * inv;
}

// ---------------------------------------------------------------------------
extern "C" void kernel_launch(void* const* d_in, const int* in_sizes, int n_in,
                              void* d_out, int out_size) {
    const float* hidden = (const float*)d_in[0];
    const int*   mask   = (const int*)d_in[1];
    float*       out    = (float*)d_out;

    dim3 grid(SPLITS, BB);
    pool_kernel<<<grid, 256>>>(hidden, mask);
    combine_kernel<<<(BB * DD) / 256, 256>>>(out);
}